// round 12
// baseline (speedup 1.0000x reference)
#include <cuda_runtime.h>
#include <cuda_fp16.h>
#include <cstdint>

#define DM   1024
#define NH   16
#define DK   64
#define BATCH 2
#define SEQ  2048
#define MROWS (BATCH*SEQ)   // 4096
#define NW   (DM*DM)
#define NX   (MROWS*DM)
#define NHD  (BATCH*NH*SEQ*DK)

// Scratch (sanctioned __device__ globals)
__device__ __half g_Wf[4*NW];               // fp16 weights (Wq,Wk,Wv,Wo)
__device__ __half g_Xhi[3*NX], g_Xlo[3*NX]; // fp16 split inputs
__device__ __half g_Chi[NX],   g_Clo[NX];   // fp16 split ctx [b,s,h*d]
__device__ __half g_Qf[NHD];                // fp16 Q (prescaled) [b,h,s,d]
__device__ __half g_Kf[NHD];                // fp16 K [b,h,s,d]
__device__ __half g_Vf[NHD];                // fp16 V TRANSPOSED [b,h,d,s]

// ---------------------------------------------------------------------------
// helpers
// ---------------------------------------------------------------------------
__device__ __forceinline__ float ex2f(float x) {
    float y;
    asm("ex2.approx.f32 %0, %1;" : "=f"(y) : "f"(x));
    return y;
}
__device__ __forceinline__ uint32_t packh2(float lo, float hi) {
    uint32_t u;
    asm("cvt.rn.f16x2.f32 %0, %1, %2;" : "=r"(u) : "f"(hi), "f"(lo));
    return u;
}
__device__ __forceinline__ void mma_fp16(float* c, const uint32_t* a,
                                         uint32_t b0, uint32_t b1) {
    asm volatile(
        "mma.sync.aligned.m16n8k16.row.col.f32.f16.f16.f32 "
        "{%0,%1,%2,%3},{%4,%5,%6,%7},{%8,%9},{%0,%1,%2,%3};"
        : "+f"(c[0]), "+f"(c[1]), "+f"(c[2]), "+f"(c[3])
        : "r"(a[0]), "r"(a[1]), "r"(a[2]), "r"(a[3]), "r"(b0), "r"(b1));
}
__device__ __forceinline__ void ldsm4(uint32_t* r, uint32_t addr) {
    asm volatile("ldmatrix.sync.aligned.m8n8.x4.shared.b16 {%0,%1,%2,%3}, [%4];"
        : "=r"(r[0]), "=r"(r[1]), "=r"(r[2]), "=r"(r[3]) : "r"(addr));
}
__device__ __forceinline__ void cpa16(uint32_t dst, const void* src) {
    asm volatile("cp.async.cg.shared.global [%0], [%1], 16;\n"
                 :: "r"(dst), "l"(src));
}
#define CP_COMMIT() asm volatile("cp.async.commit_group;\n" ::: "memory")
#define CP_WAIT1()  asm volatile("cp.async.wait_group 1;\n" ::: "memory")
#define CP_WAIT2()  asm volatile("cp.async.wait_group 2;\n" ::: "memory")

// ---------------------------------------------------------------------------
// prep: z 0-3 -> weights fp16 single; z 4-6 -> inputs fp16 hi/lo split.
// ---------------------------------------------------------------------------
__global__ __launch_bounds__(256)
void prep(const float* __restrict__ Wq, const float* __restrict__ Wk,
          const float* __restrict__ Wv, const float* __restrict__ Wo,
          const float* __restrict__ Xq, const float* __restrict__ Xk,
          const float* __restrict__ Xv)
{
    const int z = blockIdx.z;
    const float* src = (z==0)?Wq:(z==1)?Wk:(z==2)?Wv:(z==3)?Wo:
                       (z==4)?Xq:(z==5)?Xk:Xv;
    const int n4 = ((z < 4) ? NW : NX) >> 2;
    const int stride = gridDim.x * blockDim.x;
    if (z < 4) {
        __half* dw = g_Wf + (size_t)z*NW;
        for (int i = blockIdx.x*blockDim.x + threadIdx.x; i < n4; i += stride) {
            float4 v = ((const float4*)src)[i];
            uint2 u;
            u.x = packh2(v.x, v.y);
            u.y = packh2(v.z, v.w);
            *(uint2*)&dw[(size_t)i*4] = u;
        }
    } else {
        __half* dh = g_Xhi + (size_t)(z-4)*NX;
        __half* dl = g_Xlo + (size_t)(z-4)*NX;
        for (int i = blockIdx.x*blockDim.x + threadIdx.x; i < n4; i += stride) {
            float4 v = ((const float4*)src)[i];
            __half h0 = __float2half_rn(v.x);
            __half h1 = __float2half_rn(v.y);
            __half h2 = __float2half_rn(v.z);
            __half h3 = __float2half_rn(v.w);
            uint2 uh, ul;
            uh.x = ((uint32_t)__half_as_ushort(h1) << 16) | __half_as_ushort(h0);
            uh.y = ((uint32_t)__half_as_ushort(h3) << 16) | __half_as_ushort(h2);
            ul.x = packh2(v.x - __half2float(h0), v.y - __half2float(h1));
            ul.y = packh2(v.z - __half2float(h2), v.w - __half2float(h3));
            *(uint2*)&dh[(size_t)i*4] = uh;
            *(uint2*)&dl[(size_t)i*4] = ul;
        }
    }
}

// ---------------------------------------------------------------------------
// GEMM on mma.sync fp16 m16n8k16 + ldmatrix, 4-stage cp.async pipeline.
// A = Ahi+Alo (fp16 split), W single fp16, 2 products into fp32 acc.
// Block 128m x 64n, K-chunk 32 (2 k16 slabs), 32 chunks, ONE sync/chunk
// (stage target (kc+3)%4 has no live readers past the iter-kc barrier).
// Prefetch distance 3 chunks. 8 warps as 4m x 2n. Pitch 20 words
// (LDSM phases hit bank-groups (5r)%8 -> conflict-free).
// ---------------------------------------------------------------------------
#define PW2 20
#define S_A2 (128*PW2)                 // 2560 words per A operand
#define S_W2 (64*PW2)                  // 1280 words W
#define STG2 (2*S_A2 + S_W2)           // 6400 words per stage
#define GEMM_SMEM_BYTES (4*STG2*4)     // 102400

__global__ __launch_bounds__(256, 2)
void gemm_fp16(int mode, const float* __restrict__ b0p,
               const float* __restrict__ b1p, const float* __restrict__ b2p,
               float* __restrict__ outp)
{
    extern __shared__ uint32_t gsm[];

    const int z = blockIdx.z;
    const __half* Ahi = mode ? (g_Xhi + (size_t)z*NX) : g_Chi;
    const __half* Alo = mode ? (g_Xlo + (size_t)z*NX) : g_Clo;
    const int wsel = mode ? z : 3;
    const __half* WG = g_Wf + (size_t)wsel*NW;
    const float* bias = mode ? ((z==0)?b0p:(z==1)?b1p:b2p) : b0p;

    const int m0 = blockIdx.y * 128;
    const int n0 = blockIdx.x * 64;
    const int tid = threadIdx.x;
    const int w = tid >> 5;
    const int lane = tid & 31;
    const int g = lane >> 2, tg = lane & 3;
    const int wm = w & 3;
    const int wn = w >> 2;

    const uint32_t sbase = (uint32_t)__cvta_generic_to_shared(gsm);

    // LDSM lane addressing (words within stage)
    const uint32_t aOffW = (uint32_t)((wm*32 + (lane&7) + ((lane>>3)&1)*8)*PW2
                                      + (lane>>4)*4);
    const uint32_t wOffW = (uint32_t)((wn*32 + ((lane>>4)&1)*8 + (lane&7))*PW2
                                      + ((lane>>3)&1)*4);

    // stage chunk kc (k-offset kc*32 fp16) into stage s
    auto stage = [&](int kc, int s) {
        int k0 = kc * 32;
        uint32_t bb = sbase + (uint32_t)(s * STG2) * 4u;
        // A hi/lo: 128 rows x 4 granules = 512 each, 2/thread
#pragma unroll
        for (int i = 0; i < 2; i++) {
            int f = tid + i*256;
            int r = f >> 2, ch = f & 3;
            uint32_t d = bb + (uint32_t)(r*PW2 + ch*4)*4u;
            size_t so = (size_t)(m0 + r)*DM + k0 + ch*8;
            cpa16(d, Ahi + so);
            cpa16(d + S_A2*4u, Alo + so);
        }
        // W: 64 rows x 4 granules = 256, 1/thread
        {
            int r = tid >> 2, ch = tid & 3;
            uint32_t d = bb + (uint32_t)(r*PW2 + ch*4)*4u;
            cpa16(d + 2*S_A2*4u, WG + (size_t)(n0 + r)*DM + k0 + ch*8);
        }
    };

    float acc[2][4][4];
#pragma unroll
    for (int mi = 0; mi < 2; mi++)
#pragma unroll
        for (int nt = 0; nt < 4; nt++)
#pragma unroll
            for (int j = 0; j < 4; j++) acc[mi][nt][j] = 0.f;

    stage(0, 0); CP_COMMIT();
    stage(1, 1); CP_COMMIT();
    stage(2, 2); CP_COMMIT();

    const int NCH = DM/32;   // 32 chunks
    for (int kc = 0; kc < NCH; kc++) {
        CP_WAIT2();          // chunk kc complete (kc+1, kc+2 may still fly)
        __syncthreads();     // chunk kc visible; buffer (kc-1)%4 reader-free

        uint32_t bb = sbase + (uint32_t)((kc & 3) * STG2) * 4u;
        uint32_t aH = bb + aOffW*4u;
        uint32_t aL = aH + S_A2*4u;
        uint32_t wB = bb + 2*S_A2*4u + wOffW*4u;

#pragma unroll
        for (int ks = 0; ks < 2; ks++) {
            uint32_t off = (uint32_t)(ks*8)*4u;
            uint32_t afh[2][4], afl[2][4], wb[2][4];
            ldsm4(afh[0], aH + off);
            ldsm4(afh[1], aH + (uint32_t)(16*PW2)*4u + off);
            ldsm4(afl[0], aL + off);
            ldsm4(afl[1], aL + (uint32_t)(16*PW2)*4u + off);
            ldsm4(wb[0], wB + off);                            // nt0, nt1
            ldsm4(wb[1], wB + (uint32_t)(16*PW2)*4u + off);    // nt2, nt3
#pragma unroll
            for (int p = 0; p < 2; p++) {
#pragma unroll
                for (int q = 0; q < 2; q++) {
                    uint32_t b0 = wb[p][q*2], b1 = wb[p][q*2+1];
                    int nt = p*2 + q;
#pragma unroll
                    for (int mi = 0; mi < 2; mi++) {
                        mma_fp16(acc[mi][nt], afh[mi], b0, b1);
                        mma_fp16(acc[mi][nt], afl[mi], b0, b1);
                    }
                }
            }
        }

        // prefetch chunk kc+3 into the buffer just freed
        if (kc + 3 < NCH) stage(kc + 3, (kc + 3) & 3);
        CP_COMMIT();         // uniform depth (possibly empty)
    }

    // epilogue
    const float QSCALE = 0.125f * 1.4426950408889634f;
    const int h = blockIdx.x;
#pragma unroll
    for (int nt = 0; nt < 4; nt++) {
        int nc = wn*32 + nt*8 + 2*tg;
        float bb0 = bias[n0 + nc], bb1 = bias[n0 + nc + 1];
#pragma unroll
        for (int mi = 0; mi < 2; mi++) {
            int mA = m0 + wm*32 + mi*16 + g;
            int mB = mA + 8;
            float x0 = acc[mi][nt][0] + bb0, x1 = acc[mi][nt][1] + bb1;
            float y0 = acc[mi][nt][2] + bb0, y1 = acc[mi][nt][3] + bb1;
            if (mode) {
                int bA = mA >> 11, sA = mA & (SEQ-1);
                int sB = sA + 8;
                if (z == 2) {
                    size_t vb = ((size_t)(bA*NH + h)) * DK;
                    g_Vf[(vb + nc  )*SEQ + sA] = __float2half_rn(x0);
                    g_Vf[(vb + nc+1)*SEQ + sA] = __float2half_rn(x1);
                    g_Vf[(vb + nc  )*SEQ + sB] = __float2half_rn(y0);
                    g_Vf[(vb + nc+1)*SEQ + sB] = __float2half_rn(y1);
                } else {
                    __half* dst = (z == 0) ? g_Qf : g_Kf;
                    float sc = (z == 0) ? QSCALE : 1.0f;
                    size_t oA = (((size_t)(bA*NH + h)) * SEQ + sA) * DK + nc;
                    size_t oB = (((size_t)(bA*NH + h)) * SEQ + sB) * DK + nc;
                    *(uint32_t*)&dst[oA] = packh2(x0*sc, x1*sc);
                    *(uint32_t*)&dst[oB] = packh2(y0*sc, y1*sc);
                }
            } else {
                *(float2*)&outp[(size_t)mA * DM + n0 + nc] = make_float2(x0, x1);
                *(float2*)&outp[(size_t)mB * DM + n0 + nc] = make_float2(y0, y1);
            }
        }
    }
}

// ---------------------------------------------------------------------------
// Flash attention on fp16 m16n8k16 + ldmatrix (unchanged from R10).
// ---------------------------------------------------------------------------
#define PW 36
#define AQ_SZ (128*PW)
#define AK_SZ (64*PW)
#define ATTN_SMEM_BYTES ((AQ_SZ + 4*AK_SZ)*4)   // 55296

__global__ __launch_bounds__(256, 2)
void attn_fp16()
{
    extern __shared__ uint32_t sm[];

    const int bh = blockIdx.y;
    const int q0 = blockIdx.x * 128;
    const size_t base = (size_t)bh * SEQ * DK;     // [b,h,s,d] Q/K
    const size_t vbase = (size_t)bh * DK * SEQ;    // [b,h,d,s] V
    const int tid = threadIdx.x;
    const int w = tid >> 5;
    const int lane = tid & 31;
    const int g = lane >> 2, tg = lane & 3;

    const uint32_t sbase = (uint32_t)__cvta_generic_to_shared(sm);

    const uint32_t qOffW = (uint32_t)((w*16 + (lane&7) + ((lane>>3)&1)*8)*PW
                                      + (lane>>4)*4);
    const uint32_t bOffW = (uint32_t)((((lane>>4)&1)*8 + (lane&7))*PW
                                      + ((lane>>3)&1)*4);

    auto stageKV = [&](int t, int b) {
        int s0 = t * 64;
        uint32_t kB = sbase + ((AQ_SZ + (b ? AK_SZ : 0)) << 2);
        uint32_t vB = sbase + ((AQ_SZ + 2*AK_SZ + (b ? AK_SZ : 0)) << 2);
#pragma unroll
        for (int i = 0; i < 2; i++) {
            int f = tid + i*256;
            int r = f >> 3, ch = f & 7;
            uint32_t off = (uint32_t)(r*PW + ch*4)*4u;
            cpa16(kB + off, g_Kf + base + (size_t)(s0 + r)*DK + ch*8);
            cpa16(vB + off, g_Vf + vbase + (size_t)r*SEQ + s0 + ch*8);
        }
    };

#pragma unroll
    for (int i = 0; i < 4; i++) {
        int f = tid + i*256;
        int r = f >> 3, ch = f & 7;
        cpa16(sbase + (uint32_t)(r*PW + ch*4)*4u,
              g_Qf + base + (size_t)(q0 + r)*DK + ch*8);
    }
    stageKV(0, 0);
    CP_COMMIT();

    float of[8][4];
#pragma unroll
    for (int dt = 0; dt < 8; dt++)
#pragma unroll
        for (int j = 0; j < 4; j++) of[dt][j] = 0.f;
    float m0 = -1e30f, m1 = -1e30f, l0 = 0.f, l1 = 0.f;

    const int NT = SEQ/64;
    for (int t = 0; t < NT; t++) {
        if (t + 1 < NT) stageKV(t + 1, (t + 1) & 1);
        CP_COMMIT();
        CP_WAIT1();
        __syncthreads();

        const int b = t & 1;
        uint32_t qA = sbase + qOffW*4u;
        uint32_t kA = sbase + ((AQ_SZ + (b ? AK_SZ : 0)) << 2) + bOffW*4u;
        uint32_t vA = sbase + ((AQ_SZ + 2*AK_SZ + (b ? AK_SZ : 0)) << 2) + bOffW*4u;

        float sacc[8][4];
#pragma unroll
        for (int nt = 0; nt < 8; nt++)
#pragma unroll
            for (int j = 0; j < 4; j++) sacc[nt][j] = 0.f;
#pragma unroll
        for (int ks = 0; ks < 4; ks++) {
            uint32_t off = (uint32_t)(ks*8)*4u;
            uint32_t qf[4];
            ldsm4(qf, qA + off);
#pragma unroll
            for (int p = 0; p < 4; p++) {
                uint32_t kb[4];
                ldsm4(kb, kA + (uint32_t)(p*16*PW)*4u + off);
                mma_fp16(sacc[2*p],   qf, kb[0], kb[1]);
                mma_fp16(sacc[2*p+1], qf, kb[2], kb[3]);
            }
        }

        float tm0 = -1e30f, tm1 = -1e30f;
#pragma unroll
        for (int nt = 0; nt < 8; nt++) {
            tm0 = fmaxf(tm0, fmaxf(sacc[nt][0], sacc[nt][1]));
            tm1 = fmaxf(tm1, fmaxf(sacc[nt][2], sacc[nt][3]));
        }
        tm0 = fmaxf(tm0, __shfl_xor_sync(0xffffffffu, tm0, 1));
        tm0 = fmaxf(tm0, __shfl_xor_sync(0xffffffffu, tm0, 2));
        tm1 = fmaxf(tm1, __shfl_xor_sync(0xffffffffu, tm1, 1));
        tm1 = fmaxf(tm1, __shfl_xor_sync(0xffffffffu, tm1, 2));

        float mn0 = fmaxf(m0, tm0), mn1 = fmaxf(m1, tm1);
        float a0 = ex2f(m0 - mn0), a1 = ex2f(m1 - mn1);
        m0 = mn0; m1 = mn1;

        float rs0 = 0.f, rs1 = 0.f;
#pragma unroll
        for (int nt = 0; nt < 8; nt++) {
            float p0 = ex2f(sacc[nt][0] - mn0);
            float p1 = ex2f(sacc[nt][1] - mn0);
            float p2 = ex2f(sacc[nt][2] - mn1);
            float p3 = ex2f(sacc[nt][3] - mn1);
            sacc[nt][0] = p0; sacc[nt][1] = p1;
            sacc[nt][2] = p2; sacc[nt][3] = p3;
            rs0 += p0 + p1;
            rs1 += p2 + p3;
        }
        rs0 += __shfl_xor_sync(0xffffffffu, rs0, 1);
        rs0 += __shfl_xor_sync(0xffffffffu, rs0, 2);
        rs1 += __shfl_xor_sync(0xffffffffu, rs1, 1);
        rs1 += __shfl_xor_sync(0xffffffffu, rs1, 2);
        l0 = l0 * a0 + rs0;
        l1 = l1 * a1 + rs1;
#pragma unroll
        for (int dt = 0; dt < 8; dt++) {
            of[dt][0] *= a0; of[dt][1] *= a0;
            of[dt][2] *= a1; of[dt][3] *= a1;
        }

#pragma unroll
        for (int ks = 0; ks < 4; ks++) {
            uint32_t pa[4];
            pa[0] = packh2(sacc[2*ks  ][0], sacc[2*ks  ][1]);
            pa[1] = packh2(sacc[2*ks  ][2], sacc[2*ks  ][3]);
            pa[2] = packh2(sacc[2*ks+1][0], sacc[2*ks+1][1]);
            pa[3] = packh2(sacc[2*ks+1][2], sacc[2*ks+1][3]);
            uint32_t off = (uint32_t)(ks*8)*4u;
#pragma unroll
            for (int p = 0; p < 4; p++) {
                uint32_t vb[4];
                ldsm4(vb, vA + (uint32_t)(p*16*PW)*4u + off);
                mma_fp16(of[2*p],   pa, vb[0], vb[1]);
                mma_fp16(of[2*p+1], pa, vb[2], vb[3]);
            }
        }
        __syncthreads();
    }

    float inv0 = 1.0f / l0, inv1 = 1.0f / l1;
    const int b = bh >> 4, h = bh & 15;
    const int sg0 = q0 + w*16 + g, sg1 = sg0 + 8;
#pragma unroll
    for (int dt = 0; dt < 8; dt++) {
        int dcol = dt*8 + 2*tg;
        size_t i0 = ((size_t)(b*SEQ + sg0) * NH + h) * DK + dcol;
        size_t i1 = ((size_t)(b*SEQ + sg1) * NH + h) * DK + dcol;
        float x0 = of[dt][0]*inv0, x1 = of[dt][1]*inv0;
        float y0 = of[dt][2]*inv1, y1 = of[dt][3]*inv1;
        __half hx0 = __float2half_rn(x0);
        __half hx1 = __float2half_rn(x1);
        __half hy0 = __float2half_rn(y0);
        __half hy1 = __float2half_rn(y1);
        *(uint32_t*)&g_Chi[i0] = ((uint32_t)__half_as_ushort(hx1) << 16) | __half_as_ushort(hx0);
        *(uint32_t*)&g_Chi[i1] = ((uint32_t)__half_as_ushort(hy1) << 16) | __half_as_ushort(hy0);
        *(uint32_t*)&g_Clo[i0] = packh2(x0 - __half2float(hx0), x1 - __half2float(hx1));
        *(uint32_t*)&g_Clo[i1] = packh2(y0 - __half2float(hy0), y1 - __half2float(hy1));
    }
}

// ---------------------------------------------------------------------------
extern "C" void kernel_launch(void* const* d_in, const int* in_sizes, int n_in,
                              void* d_out, int out_size)
{
    const float* Xq = (const float*)d_in[0];
    const float* Xk = (const float*)d_in[1];
    const float* Xv = (const float*)d_in[2];
    const float* Wq = (const float*)d_in[3];
    const float* bq = (const float*)d_in[4];
    const float* Wk = (const float*)d_in[5];
    const float* bk = (const float*)d_in[6];
    const float* Wv = (const float*)d_in[7];
    const float* bv = (const float*)d_in[8];
    const float* Wo = (const float*)d_in[9];
    const float* bo = (const float*)d_in[10];
    float* out = (float*)d_out;

    cudaFuncSetAttribute(gemm_fp16,
                         cudaFuncAttributeMaxDynamicSharedMemorySize,
                         GEMM_SMEM_BYTES);
    cudaFuncSetAttribute(attn_fp16,
                         cudaFuncAttributeMaxDynamicSharedMemorySize,
                         ATTN_SMEM_BYTES);

    prep<<<dim3(1024, 1, 7), 256>>>(Wq, Wk, Wv, Wo, Xq, Xk, Xv);

    dim3 gq(DM/64, MROWS/128, 3);    // fused QKV: 16 x 32 x 3
    gemm_fp16<<<gq, 256, GEMM_SMEM_BYTES>>>(1, bq, bk, bv, nullptr);

    dim3 ga(SEQ/128, BATCH*NH);      // 16 x 32
    attn_fp16<<<ga, 256, ATTN_SMEM_BYTES>>>();

    dim3 gp(DM/64, MROWS/128, 1);    // out projection
    gemm_fp16<<<gp, 256, GEMM_SMEM_BYTES>>>(0, bo, bo, bo, out);
}

// round 13
// speedup vs baseline: 1.4531x; 1.4531x over previous
#include <cuda_runtime.h>
#include <cuda_fp16.h>
#include <cstdint>

#define DM   1024
#define NH   16
#define DK   64
#define BATCH 2
#define SEQ  2048
#define MROWS (BATCH*SEQ)   // 4096
#define NW   (DM*DM)
#define NX   (MROWS*DM)
#define NHD  (BATCH*NH*SEQ*DK)

// Scratch (sanctioned __device__ globals)
__device__ __half g_Wf[4*NW];    // fp16 weights (Wq,Wk,Wv,Wo)
__device__ __half g_Xf[3*NX];    // fp16 inputs
__device__ __half g_Cf[NX];      // fp16 ctx [b,s,h*d]
__device__ __half g_Qf[NHD];     // fp16 Q (prescaled) [b,h,s,d]
__device__ __half g_Kf[NHD];     // fp16 K [b,h,s,d]
__device__ __half g_Vf[NHD];     // fp16 V TRANSPOSED [b,h,d,s]

// ---------------------------------------------------------------------------
// helpers
// ---------------------------------------------------------------------------
__device__ __forceinline__ float ex2f(float x) {
    float y;
    asm("ex2.approx.f32 %0, %1;" : "=f"(y) : "f"(x));
    return y;
}
__device__ __forceinline__ uint32_t packh2(float lo, float hi) {
    uint32_t u;
    asm("cvt.rn.f16x2.f32 %0, %1, %2;" : "=r"(u) : "f"(hi), "f"(lo));
    return u;
}
__device__ __forceinline__ void mma_fp16(float* c, const uint32_t* a,
                                         uint32_t b0, uint32_t b1) {
    asm volatile(
        "mma.sync.aligned.m16n8k16.row.col.f32.f16.f16.f32 "
        "{%0,%1,%2,%3},{%4,%5,%6,%7},{%8,%9},{%0,%1,%2,%3};"
        : "+f"(c[0]), "+f"(c[1]), "+f"(c[2]), "+f"(c[3])
        : "r"(a[0]), "r"(a[1]), "r"(a[2]), "r"(a[3]), "r"(b0), "r"(b1));
}
__device__ __forceinline__ void ldsm4(uint32_t* r, uint32_t addr) {
    asm volatile("ldmatrix.sync.aligned.m8n8.x4.shared.b16 {%0,%1,%2,%3}, [%4];"
        : "=r"(r[0]), "=r"(r[1]), "=r"(r[2]), "=r"(r[3]) : "r"(addr));
}
__device__ __forceinline__ void cpa16(uint32_t dst, const void* src) {
    asm volatile("cp.async.cg.shared.global [%0], [%1], 16;\n"
                 :: "r"(dst), "l"(src));
}
#define CP_COMMIT() asm volatile("cp.async.commit_group;\n" ::: "memory")
#define CP_WAIT1()  asm volatile("cp.async.wait_group 1;\n" ::: "memory")
#define CP_WAIT2()  asm volatile("cp.async.wait_group 2;\n" ::: "memory")

// ---------------------------------------------------------------------------
// prep: plain fp16 conversion. z 0-3 weights, z 4-6 inputs.
// ---------------------------------------------------------------------------
__global__ __launch_bounds__(256)
void prep(const float* __restrict__ Wq, const float* __restrict__ Wk,
          const float* __restrict__ Wv, const float* __restrict__ Wo,
          const float* __restrict__ Xq, const float* __restrict__ Xk,
          const float* __restrict__ Xv)
{
    const int z = blockIdx.z;
    const float* src = (z==0)?Wq:(z==1)?Wk:(z==2)?Wv:(z==3)?Wo:
                       (z==4)?Xq:(z==5)?Xk:Xv;
    __half* dst = (z < 4) ? (g_Wf + (size_t)z*NW) : (g_Xf + (size_t)(z-4)*NX);
    const int n4 = ((z < 4) ? NW : NX) >> 2;
    const int stride = gridDim.x * blockDim.x;
    for (int i = blockIdx.x*blockDim.x + threadIdx.x; i < n4; i += stride) {
        float4 v = ((const float4*)src)[i];
        uint2 u;
        u.x = packh2(v.x, v.y);
        u.y = packh2(v.z, v.w);
        *(uint2*)&dst[(size_t)i*4] = u;
    }
}

// ---------------------------------------------------------------------------
// GEMM on mma.sync fp16 m16n8k16 + ldmatrix, 4-stage cp.async pipeline.
// Single fp16 (no split). Block tile 128m x 128n, K-chunk 32, 32 chunks,
// ONE sync per chunk (stage target (kc+3)%4 reader-free past the barrier).
// 8 warps as 4m x 2n -> warp tile 32m x 64n (8 n-tiles, 64 fp32 accs).
// Pitch 20 words/row: LDSM phases hit bank-groups (5r)%8 -> conflict-free.
// mode=1: z picks Xq->Qf(prescaled), Xk->Kf, Xv->Vf(transposed [b,h,d,s])
// mode=0: (ctx, Wo) -> out fp32 + bias
// ---------------------------------------------------------------------------
#define PW2 20
#define S_A2 (128*PW2)                 // 2560 words A
#define STG2 (2*S_A2)                  // 5120 words per stage (A + W)
#define GEMM_SMEM_BYTES (4*STG2*4)     // 81920

__global__ __launch_bounds__(256, 2)
void gemm_fp16(int mode, const float* __restrict__ b0p,
               const float* __restrict__ b1p, const float* __restrict__ b2p,
               float* __restrict__ outp)
{
    extern __shared__ uint32_t gsm[];

    const int z = blockIdx.z;
    const __half* Af = mode ? (g_Xf + (size_t)z*NX) : g_Cf;
    const int wsel = mode ? z : 3;
    const __half* WG = g_Wf + (size_t)wsel*NW;
    const float* bias = mode ? ((z==0)?b0p:(z==1)?b1p:b2p) : b0p;

    const int m0 = blockIdx.y * 128;
    const int n0 = blockIdx.x * 128;
    const int tid = threadIdx.x;
    const int w = tid >> 5;
    const int lane = tid & 31;
    const int g = lane >> 2, tg = lane & 3;
    const int wm = w & 3;              // 4 m-groups of 32 rows
    const int wn = w >> 2;             // 2 n-groups of 64 cols

    const uint32_t sbase = (uint32_t)__cvta_generic_to_shared(gsm);

    // LDSM lane addressing (words within stage)
    const uint32_t aOffW = (uint32_t)((wm*32 + (lane&7) + ((lane>>3)&1)*8)*PW2
                                      + (lane>>4)*4);
    const uint32_t wOffW = (uint32_t)((wn*64 + ((lane>>4)&1)*8 + (lane&7))*PW2
                                      + ((lane>>3)&1)*4);

    // stage chunk kc (k-offset kc*32 fp16) into stage s
    auto stage = [&](int kc, int s) {
        int k0 = kc * 32;
        uint32_t bb = sbase + (uint32_t)(s * STG2) * 4u;
        // A: 128 rows x 4 granules = 512, 2/thread
#pragma unroll
        for (int i = 0; i < 2; i++) {
            int f = tid + i*256;
            int r = f >> 2, ch = f & 3;
            cpa16(bb + (uint32_t)(r*PW2 + ch*4)*4u,
                  Af + (size_t)(m0 + r)*DM + k0 + ch*8);
        }
        // W: 128 rows x 4 granules = 512, 2/thread
#pragma unroll
        for (int i = 0; i < 2; i++) {
            int f = tid + i*256;
            int r = f >> 2, ch = f & 3;
            cpa16(bb + S_A2*4u + (uint32_t)(r*PW2 + ch*4)*4u,
                  WG + (size_t)(n0 + r)*DM + k0 + ch*8);
        }
    };

    float acc[2][8][4];
#pragma unroll
    for (int mi = 0; mi < 2; mi++)
#pragma unroll
        for (int nt = 0; nt < 8; nt++)
#pragma unroll
            for (int j = 0; j < 4; j++) acc[mi][nt][j] = 0.f;

    stage(0, 0); CP_COMMIT();
    stage(1, 1); CP_COMMIT();
    stage(2, 2); CP_COMMIT();

    const int NCH = DM/32;   // 32 chunks
    for (int kc = 0; kc < NCH; kc++) {
        CP_WAIT2();          // chunk kc complete
        __syncthreads();     // visible; buffer (kc-1)%4 reader-free

        uint32_t bb = sbase + (uint32_t)((kc & 3) * STG2) * 4u;
        uint32_t aA = bb + aOffW*4u;
        uint32_t wB = bb + S_A2*4u + wOffW*4u;

#pragma unroll
        for (int ks = 0; ks < 2; ks++) {
            uint32_t off = (uint32_t)(ks*8)*4u;
            uint32_t af[2][4];
            ldsm4(af[0], aA + off);
            ldsm4(af[1], aA + (uint32_t)(16*PW2)*4u + off);
#pragma unroll
            for (int p = 0; p < 4; p++) {
                uint32_t wb[4];
                ldsm4(wb, wB + (uint32_t)(p*16*PW2)*4u + off);
#pragma unroll
                for (int q = 0; q < 2; q++) {
                    int nt = p*2 + q;
#pragma unroll
                    for (int mi = 0; mi < 2; mi++)
                        mma_fp16(acc[mi][nt], af[mi], wb[q*2], wb[q*2+1]);
                }
            }
        }

        if (kc + 3 < NCH) stage(kc + 3, (kc + 3) & 3);
        CP_COMMIT();         // uniform depth (possibly empty)
    }

    // epilogue
    const float QSCALE = 0.125f * 1.4426950408889634f;
#pragma unroll
    for (int nt = 0; nt < 8; nt++) {
        int ncl = wn*64 + nt*8 + 2*tg;      // col within 128-wide tile
        int gn = n0 + ncl;                  // global out column
        float bb0 = bias[gn], bb1 = bias[gn + 1];
#pragma unroll
        for (int mi = 0; mi < 2; mi++) {
            int mA = m0 + wm*32 + mi*16 + g;
            int mB = mA + 8;
            float x0 = acc[mi][nt][0] + bb0, x1 = acc[mi][nt][1] + bb1;
            float y0 = acc[mi][nt][2] + bb0, y1 = acc[mi][nt][3] + bb1;
            if (mode) {
                int bA = mA >> 11, sA = mA & (SEQ-1);
                int sB = sA + 8;
                int h = gn >> 6, d = gn & 63;
                if (z == 2) {
                    size_t vb = ((size_t)(bA*NH + h)) * DK;
                    g_Vf[(vb + d  )*SEQ + sA] = __float2half_rn(x0);
                    g_Vf[(vb + d+1)*SEQ + sA] = __float2half_rn(x1);
                    g_Vf[(vb + d  )*SEQ + sB] = __float2half_rn(y0);
                    g_Vf[(vb + d+1)*SEQ + sB] = __float2half_rn(y1);
                } else {
                    __half* dst = (z == 0) ? g_Qf : g_Kf;
                    float sc = (z == 0) ? QSCALE : 1.0f;
                    size_t oA = (((size_t)(bA*NH + h)) * SEQ + sA) * DK + d;
                    size_t oB = (((size_t)(bA*NH + h)) * SEQ + sB) * DK + d;
                    *(uint32_t*)&dst[oA] = packh2(x0*sc, x1*sc);
                    *(uint32_t*)&dst[oB] = packh2(y0*sc, y1*sc);
                }
            } else {
                *(float2*)&outp[(size_t)mA * DM + gn] = make_float2(x0, x1);
                *(float2*)&outp[(size_t)mB * DM + gn] = make_float2(y0, y1);
            }
        }
    }
}

// ---------------------------------------------------------------------------
// Flash attention on fp16 m16n8k16 + ldmatrix (unchanged from R10 champion,
// except ctx epilogue writes single fp16).
// ---------------------------------------------------------------------------
#define PW 36
#define AQ_SZ (128*PW)
#define AK_SZ (64*PW)
#define ATTN_SMEM_BYTES ((AQ_SZ + 4*AK_SZ)*4)   // 55296

__global__ __launch_bounds__(256, 2)
void attn_fp16()
{
    extern __shared__ uint32_t sm[];

    const int bh = blockIdx.y;
    const int q0 = blockIdx.x * 128;
    const size_t base = (size_t)bh * SEQ * DK;     // [b,h,s,d] Q/K
    const size_t vbase = (size_t)bh * DK * SEQ;    // [b,h,d,s] V
    const int tid = threadIdx.x;
    const int w = tid >> 5;
    const int lane = tid & 31;
    const int g = lane >> 2, tg = lane & 3;

    const uint32_t sbase = (uint32_t)__cvta_generic_to_shared(sm);

    const uint32_t qOffW = (uint32_t)((w*16 + (lane&7) + ((lane>>3)&1)*8)*PW
                                      + (lane>>4)*4);
    const uint32_t bOffW = (uint32_t)((((lane>>4)&1)*8 + (lane&7))*PW
                                      + ((lane>>3)&1)*4);

    auto stageKV = [&](int t, int b) {
        int s0 = t * 64;
        uint32_t kB = sbase + ((AQ_SZ + (b ? AK_SZ : 0)) << 2);
        uint32_t vB = sbase + ((AQ_SZ + 2*AK_SZ + (b ? AK_SZ : 0)) << 2);
#pragma unroll
        for (int i = 0; i < 2; i++) {
            int f = tid + i*256;
            int r = f >> 3, ch = f & 7;
            uint32_t off = (uint32_t)(r*PW + ch*4)*4u;
            cpa16(kB + off, g_Kf + base + (size_t)(s0 + r)*DK + ch*8);
            cpa16(vB + off, g_Vf + vbase + (size_t)r*SEQ + s0 + ch*8);
        }
    };

#pragma unroll
    for (int i = 0; i < 4; i++) {
        int f = tid + i*256;
        int r = f >> 3, ch = f & 7;
        cpa16(sbase + (uint32_t)(r*PW + ch*4)*4u,
              g_Qf + base + (size_t)(q0 + r)*DK + ch*8);
    }
    stageKV(0, 0);
    CP_COMMIT();

    float of[8][4];
#pragma unroll
    for (int dt = 0; dt < 8; dt++)
#pragma unroll
        for (int j = 0; j < 4; j++) of[dt][j] = 0.f;
    float m0 = -1e30f, m1 = -1e30f, l0 = 0.f, l1 = 0.f;

    const int NT = SEQ/64;
    for (int t = 0; t < NT; t++) {
        if (t + 1 < NT) stageKV(t + 1, (t + 1) & 1);
        CP_COMMIT();
        CP_WAIT1();
        __syncthreads();

        const int b = t & 1;
        uint32_t qA = sbase + qOffW*4u;
        uint32_t kA = sbase + ((AQ_SZ + (b ? AK_SZ : 0)) << 2) + bOffW*4u;
        uint32_t vA = sbase + ((AQ_SZ + 2*AK_SZ + (b ? AK_SZ : 0)) << 2) + bOffW*4u;

        float sacc[8][4];
#pragma unroll
        for (int nt = 0; nt < 8; nt++)
#pragma unroll
            for (int j = 0; j < 4; j++) sacc[nt][j] = 0.f;
#pragma unroll
        for (int ks = 0; ks < 4; ks++) {
            uint32_t off = (uint32_t)(ks*8)*4u;
            uint32_t qf[4];
            ldsm4(qf, qA + off);
#pragma unroll
            for (int p = 0; p < 4; p++) {
                uint32_t kb[4];
                ldsm4(kb, kA + (uint32_t)(p*16*PW)*4u + off);
                mma_fp16(sacc[2*p],   qf, kb[0], kb[1]);
                mma_fp16(sacc[2*p+1], qf, kb[2], kb[3]);
            }
        }

        float tm0 = -1e30f, tm1 = -1e30f;
#pragma unroll
        for (int nt = 0; nt < 8; nt++) {
            tm0 = fmaxf(tm0, fmaxf(sacc[nt][0], sacc[nt][1]));
            tm1 = fmaxf(tm1, fmaxf(sacc[nt][2], sacc[nt][3]));
        }
        tm0 = fmaxf(tm0, __shfl_xor_sync(0xffffffffu, tm0, 1));
        tm0 = fmaxf(tm0, __shfl_xor_sync(0xffffffffu, tm0, 2));
        tm1 = fmaxf(tm1, __shfl_xor_sync(0xffffffffu, tm1, 1));
        tm1 = fmaxf(tm1, __shfl_xor_sync(0xffffffffu, tm1, 2));

        float mn0 = fmaxf(m0, tm0), mn1 = fmaxf(m1, tm1);
        float a0 = ex2f(m0 - mn0), a1 = ex2f(m1 - mn1);
        m0 = mn0; m1 = mn1;

        float rs0 = 0.f, rs1 = 0.f;
#pragma unroll
        for (int nt = 0; nt < 8; nt++) {
            float p0 = ex2f(sacc[nt][0] - mn0);
            float p1 = ex2f(sacc[nt][1] - mn0);
            float p2 = ex2f(sacc[nt][2] - mn1);
            float p3 = ex2f(sacc[nt][3] - mn1);
            sacc[nt][0] = p0; sacc[nt][1] = p1;
            sacc[nt][2] = p2; sacc[nt][3] = p3;
            rs0 += p0 + p1;
            rs1 += p2 + p3;
        }
        rs0 += __shfl_xor_sync(0xffffffffu, rs0, 1);
        rs0 += __shfl_xor_sync(0xffffffffu, rs0, 2);
        rs1 += __shfl_xor_sync(0xffffffffu, rs1, 1);
        rs1 += __shfl_xor_sync(0xffffffffu, rs1, 2);
        l0 = l0 * a0 + rs0;
        l1 = l1 * a1 + rs1;
#pragma unroll
        for (int dt = 0; dt < 8; dt++) {
            of[dt][0] *= a0; of[dt][1] *= a0;
            of[dt][2] *= a1; of[dt][3] *= a1;
        }

#pragma unroll
        for (int ks = 0; ks < 4; ks++) {
            uint32_t pa[4];
            pa[0] = packh2(sacc[2*ks  ][0], sacc[2*ks  ][1]);
            pa[1] = packh2(sacc[2*ks  ][2], sacc[2*ks  ][3]);
            pa[2] = packh2(sacc[2*ks+1][0], sacc[2*ks+1][1]);
            pa[3] = packh2(sacc[2*ks+1][2], sacc[2*ks+1][3]);
            uint32_t off = (uint32_t)(ks*8)*4u;
#pragma unroll
            for (int p = 0; p < 4; p++) {
                uint32_t vb[4];
                ldsm4(vb, vA + (uint32_t)(p*16*PW)*4u + off);
                mma_fp16(of[2*p],   pa, vb[0], vb[1]);
                mma_fp16(of[2*p+1], pa, vb[2], vb[3]);
            }
        }
        __syncthreads();
    }

    // epilogue: normalize -> fp16 ctx, [b, s, h, d] concat layout
    float inv0 = 1.0f / l0, inv1 = 1.0f / l1;
    const int b = bh >> 4, h = bh & 15;
    const int sg0 = q0 + w*16 + g, sg1 = sg0 + 8;
#pragma unroll
    for (int dt = 0; dt < 8; dt++) {
        int dcol = dt*8 + 2*tg;
        size_t i0 = ((size_t)(b*SEQ + sg0) * NH + h) * DK + dcol;
        size_t i1 = ((size_t)(b*SEQ + sg1) * NH + h) * DK + dcol;
        *(uint32_t*)&g_Cf[i0] = packh2(of[dt][0]*inv0, of[dt][1]*inv0);
        *(uint32_t*)&g_Cf[i1] = packh2(of[dt][2]*inv1, of[dt][3]*inv1);
    }
}

// ---------------------------------------------------------------------------
extern "C" void kernel_launch(void* const* d_in, const int* in_sizes, int n_in,
                              void* d_out, int out_size)
{
    const float* Xq = (const float*)d_in[0];
    const float* Xk = (const float*)d_in[1];
    const float* Xv = (const float*)d_in[2];
    const float* Wq = (const float*)d_in[3];
    const float* bq = (const float*)d_in[4];
    const float* Wk = (const float*)d_in[5];
    const float* bk = (const float*)d_in[6];
    const float* Wv = (const float*)d_in[7];
    const float* bv = (const float*)d_in[8];
    const float* Wo = (const float*)d_in[9];
    const float* bo = (const float*)d_in[10];
    float* out = (float*)d_out;

    cudaFuncSetAttribute(gemm_fp16,
                         cudaFuncAttributeMaxDynamicSharedMemorySize,
                         GEMM_SMEM_BYTES);
    cudaFuncSetAttribute(attn_fp16,
                         cudaFuncAttributeMaxDynamicSharedMemorySize,
                         ATTN_SMEM_BYTES);

    prep<<<dim3(1024, 1, 7), 256>>>(Wq, Wk, Wv, Wo, Xq, Xk, Xv);

    dim3 gq(DM/128, MROWS/128, 3);   // fused QKV: 8 x 32 x 3 = 768 blocks
    gemm_fp16<<<gq, 256, GEMM_SMEM_BYTES>>>(1, bq, bk, bv, nullptr);

    dim3 ga(SEQ/128, BATCH*NH);      // 16 x 32
    attn_fp16<<<ga, 256, ATTN_SMEM_BYTES>>>();

    dim3 gp(DM/128, MROWS/128, 1);   // out projection: 256 blocks
    gemm_fp16<<<gp, 256, GEMM_SMEM_BYTES>>>(0, bo, bo, bo, out);
}

// round 14
// speedup vs baseline: 1.5247x; 1.0493x over previous
#include <cuda_runtime.h>
#include <cuda_fp16.h>
#include <cstdint>

#define DM   1024
#define NH   16
#define DK   64
#define BATCH 2
#define SEQ  2048
#define MROWS (BATCH*SEQ)   // 4096
#define NW   (DM*DM)
#define NX   (MROWS*DM)
#define NHD  (BATCH*NH*SEQ*DK)

// Scratch (sanctioned __device__ globals)
__device__ __half g_Wf[4*NW];    // fp16 weights (Wq,Wk,Wv,Wo)
__device__ __half g_Xf[3*NX];    // fp16 inputs
__device__ __half g_Cf[NX];      // fp16 ctx [b,s,h*d]
__device__ __half g_Qf[NHD];     // fp16 Q (prescaled) [b,h,s,d]
__device__ __half g_Kf[NHD];     // fp16 K [b,h,s,d]
__device__ __half g_Vf[NHD];     // fp16 V TRANSPOSED [b,h,d,s]

// ---------------------------------------------------------------------------
// helpers
// ---------------------------------------------------------------------------
__device__ __forceinline__ float ex2f(float x) {
    float y;
    asm("ex2.approx.f32 %0, %1;" : "=f"(y) : "f"(x));
    return y;
}
__device__ __forceinline__ uint32_t h2ex2(uint32_t x) {
    uint32_t y;
    asm("ex2.approx.f16x2 %0, %1;" : "=r"(y) : "r"(x));
    return y;
}
__device__ __forceinline__ uint32_t packh2(float lo, float hi) {
    uint32_t u;
    asm("cvt.rn.f16x2.f32 %0, %1, %2;" : "=r"(u) : "f"(hi), "f"(lo));
    return u;
}
__device__ __forceinline__ float2 h2unpack(uint32_t u) {
    __half2 h = *reinterpret_cast<__half2*>(&u);
    return __half22float2(h);
}
__device__ __forceinline__ void mma_fp16(float* c, const uint32_t* a,
                                         uint32_t b0, uint32_t b1) {
    asm volatile(
        "mma.sync.aligned.m16n8k16.row.col.f32.f16.f16.f32 "
        "{%0,%1,%2,%3},{%4,%5,%6,%7},{%8,%9},{%0,%1,%2,%3};"
        : "+f"(c[0]), "+f"(c[1]), "+f"(c[2]), "+f"(c[3])
        : "r"(a[0]), "r"(a[1]), "r"(a[2]), "r"(a[3]), "r"(b0), "r"(b1));
}
__device__ __forceinline__ void ldsm4(uint32_t* r, uint32_t addr) {
    asm volatile("ldmatrix.sync.aligned.m8n8.x4.shared.b16 {%0,%1,%2,%3}, [%4];"
        : "=r"(r[0]), "=r"(r[1]), "=r"(r[2]), "=r"(r[3]) : "r"(addr));
}
__device__ __forceinline__ void cpa16(uint32_t dst, const void* src) {
    asm volatile("cp.async.cg.shared.global [%0], [%1], 16;\n"
                 :: "r"(dst), "l"(src));
}
#define CP_COMMIT() asm volatile("cp.async.commit_group;\n" ::: "memory")
#define CP_WAIT1()  asm volatile("cp.async.wait_group 1;\n" ::: "memory")
#define CP_WAIT2()  asm volatile("cp.async.wait_group 2;\n" ::: "memory")

// ---------------------------------------------------------------------------
// prep: plain fp16 conversion. z 0-3 weights, z 4-6 inputs.
// ---------------------------------------------------------------------------
__global__ __launch_bounds__(256)
void prep(const float* __restrict__ Wq, const float* __restrict__ Wk,
          const float* __restrict__ Wv, const float* __restrict__ Wo,
          const float* __restrict__ Xq, const float* __restrict__ Xk,
          const float* __restrict__ Xv)
{
    const int z = blockIdx.z;
    const float* src = (z==0)?Wq:(z==1)?Wk:(z==2)?Wv:(z==3)?Wo:
                       (z==4)?Xq:(z==5)?Xk:Xv;
    __half* dst = (z < 4) ? (g_Wf + (size_t)z*NW) : (g_Xf + (size_t)(z-4)*NX);
    const int n4 = ((z < 4) ? NW : NX) >> 2;
    const int stride = gridDim.x * blockDim.x;
    for (int i = blockIdx.x*blockDim.x + threadIdx.x; i < n4; i += stride) {
        float4 v = ((const float4*)src)[i];
        uint2 u;
        u.x = packh2(v.x, v.y);
        u.y = packh2(v.z, v.w);
        *(uint2*)&dst[(size_t)i*4] = u;
    }
}

// ---------------------------------------------------------------------------
// GEMM on mma.sync fp16 m16n8k16 + ldmatrix, 4-stage cp.async pipeline.
// (unchanged from R12 champion)
// ---------------------------------------------------------------------------
#define PW2 20
#define S_A2 (128*PW2)                 // 2560 words A
#define STG2 (2*S_A2)                  // 5120 words per stage (A + W)
#define GEMM_SMEM_BYTES (4*STG2*4)     // 81920

__global__ __launch_bounds__(256, 2)
void gemm_fp16(int mode, const float* __restrict__ b0p,
               const float* __restrict__ b1p, const float* __restrict__ b2p,
               float* __restrict__ outp)
{
    extern __shared__ uint32_t gsm[];

    const int z = blockIdx.z;
    const __half* Af = mode ? (g_Xf + (size_t)z*NX) : g_Cf;
    const int wsel = mode ? z : 3;
    const __half* WG = g_Wf + (size_t)wsel*NW;
    const float* bias = mode ? ((z==0)?b0p:(z==1)?b1p:b2p) : b0p;

    const int m0 = blockIdx.y * 128;
    const int n0 = blockIdx.x * 128;
    const int tid = threadIdx.x;
    const int w = tid >> 5;
    const int lane = tid & 31;
    const int g = lane >> 2, tg = lane & 3;
    const int wm = w & 3;
    const int wn = w >> 2;

    const uint32_t sbase = (uint32_t)__cvta_generic_to_shared(gsm);

    const uint32_t aOffW = (uint32_t)((wm*32 + (lane&7) + ((lane>>3)&1)*8)*PW2
                                      + (lane>>4)*4);
    const uint32_t wOffW = (uint32_t)((wn*64 + ((lane>>4)&1)*8 + (lane&7))*PW2
                                      + ((lane>>3)&1)*4);

    auto stage = [&](int kc, int s) {
        int k0 = kc * 32;
        uint32_t bb = sbase + (uint32_t)(s * STG2) * 4u;
#pragma unroll
        for (int i = 0; i < 2; i++) {
            int f = tid + i*256;
            int r = f >> 2, ch = f & 3;
            cpa16(bb + (uint32_t)(r*PW2 + ch*4)*4u,
                  Af + (size_t)(m0 + r)*DM + k0 + ch*8);
        }
#pragma unroll
        for (int i = 0; i < 2; i++) {
            int f = tid + i*256;
            int r = f >> 2, ch = f & 3;
            cpa16(bb + S_A2*4u + (uint32_t)(r*PW2 + ch*4)*4u,
                  WG + (size_t)(n0 + r)*DM + k0 + ch*8);
        }
    };

    float acc[2][8][4];
#pragma unroll
    for (int mi = 0; mi < 2; mi++)
#pragma unroll
        for (int nt = 0; nt < 8; nt++)
#pragma unroll
            for (int j = 0; j < 4; j++) acc[mi][nt][j] = 0.f;

    stage(0, 0); CP_COMMIT();
    stage(1, 1); CP_COMMIT();
    stage(2, 2); CP_COMMIT();

    const int NCH = DM/32;   // 32 chunks
    for (int kc = 0; kc < NCH; kc++) {
        CP_WAIT2();
        __syncthreads();

        uint32_t bb = sbase + (uint32_t)((kc & 3) * STG2) * 4u;
        uint32_t aA = bb + aOffW*4u;
        uint32_t wB = bb + S_A2*4u + wOffW*4u;

#pragma unroll
        for (int ks = 0; ks < 2; ks++) {
            uint32_t off = (uint32_t)(ks*8)*4u;
            uint32_t af[2][4];
            ldsm4(af[0], aA + off);
            ldsm4(af[1], aA + (uint32_t)(16*PW2)*4u + off);
#pragma unroll
            for (int p = 0; p < 4; p++) {
                uint32_t wb[4];
                ldsm4(wb, wB + (uint32_t)(p*16*PW2)*4u + off);
#pragma unroll
                for (int q = 0; q < 2; q++) {
                    int nt = p*2 + q;
#pragma unroll
                    for (int mi = 0; mi < 2; mi++)
                        mma_fp16(acc[mi][nt], af[mi], wb[q*2], wb[q*2+1]);
                }
            }
        }

        if (kc + 3 < NCH) stage(kc + 3, (kc + 3) & 3);
        CP_COMMIT();
    }

    // epilogue
    const float QSCALE = 0.125f * 1.4426950408889634f;
#pragma unroll
    for (int nt = 0; nt < 8; nt++) {
        int ncl = wn*64 + nt*8 + 2*tg;
        int gn = n0 + ncl;
        float bb0 = bias[gn], bb1 = bias[gn + 1];
#pragma unroll
        for (int mi = 0; mi < 2; mi++) {
            int mA = m0 + wm*32 + mi*16 + g;
            int mB = mA + 8;
            float x0 = acc[mi][nt][0] + bb0, x1 = acc[mi][nt][1] + bb1;
            float y0 = acc[mi][nt][2] + bb0, y1 = acc[mi][nt][3] + bb1;
            if (mode) {
                int bA = mA >> 11, sA = mA & (SEQ-1);
                int sB = sA + 8;
                int h = gn >> 6, d = gn & 63;
                if (z == 2) {
                    size_t vb = ((size_t)(bA*NH + h)) * DK;
                    g_Vf[(vb + d  )*SEQ + sA] = __float2half_rn(x0);
                    g_Vf[(vb + d+1)*SEQ + sA] = __float2half_rn(x1);
                    g_Vf[(vb + d  )*SEQ + sB] = __float2half_rn(y0);
                    g_Vf[(vb + d+1)*SEQ + sB] = __float2half_rn(y1);
                } else {
                    __half* dst = (z == 0) ? g_Qf : g_Kf;
                    float sc = (z == 0) ? QSCALE : 1.0f;
                    size_t oA = (((size_t)(bA*NH + h)) * SEQ + sA) * DK + d;
                    size_t oB = (((size_t)(bA*NH + h)) * SEQ + sB) * DK + d;
                    *(uint32_t*)&dst[oA] = packh2(x0*sc, x1*sc);
                    *(uint32_t*)&dst[oB] = packh2(y0*sc, y1*sc);
                }
            } else {
                *(float2*)&outp[(size_t)mA * DM + gn] = make_float2(x0, x1);
                *(float2*)&outp[(size_t)mB * DM + gn] = make_float2(y0, y1);
            }
        }
    }
}

// ---------------------------------------------------------------------------
// Flash attention, fp16 m16n8k16 + ldmatrix, v2:
//  - triple-buffered K/V, ONE __syncthreads per tile (stage target (t+2)%3
//    is reader-free past the iteration barrier)
//  - P generated via ex2.approx.f16x2 directly in pa register format
// smem: Qs 128x36 | Ks[3] 64x36 | Vs[3] 64x36 = 73728 B; 2 blocks/SM.
// ---------------------------------------------------------------------------
#define PW 36
#define AQ_SZ (128*PW)   // 4608 words
#define AK_SZ (64*PW)    // 2304 words
#define ATTN_SMEM_BYTES ((AQ_SZ + 6*AK_SZ)*4)   // 73728

__global__ __launch_bounds__(256, 2)
void attn_fp16()
{
    extern __shared__ uint32_t sm[];

    const int bh = blockIdx.y;
    const int q0 = blockIdx.x * 128;
    const size_t base = (size_t)bh * SEQ * DK;     // [b,h,s,d] Q/K
    const size_t vbase = (size_t)bh * DK * SEQ;    // [b,h,d,s] V
    const int tid = threadIdx.x;
    const int w = tid >> 5;
    const int lane = tid & 31;
    const int g = lane >> 2, tg = lane & 3;

    const uint32_t sbase = (uint32_t)__cvta_generic_to_shared(sm);

    const uint32_t qOffW = (uint32_t)((w*16 + (lane&7) + ((lane>>3)&1)*8)*PW
                                      + (lane>>4)*4);
    const uint32_t bOffW = (uint32_t)((((lane>>4)&1)*8 + (lane&7))*PW
                                      + ((lane>>3)&1)*4);

    auto stageKV = [&](int t, int b) {
        int s0 = t * 64;
        uint32_t kB = sbase + (uint32_t)(AQ_SZ + b*AK_SZ)*4u;
        uint32_t vB = sbase + (uint32_t)(AQ_SZ + (3 + b)*AK_SZ)*4u;
#pragma unroll
        for (int i = 0; i < 2; i++) {
            int f = tid + i*256;
            int r = f >> 3, ch = f & 7;
            uint32_t off = (uint32_t)(r*PW + ch*4)*4u;
            cpa16(kB + off, g_Kf + base + (size_t)(s0 + r)*DK + ch*8);
            cpa16(vB + off, g_Vf + vbase + (size_t)r*SEQ + s0 + ch*8);
        }
    };

    // prologue: Q + tile0 (group 0), tile1 (group 1)
#pragma unroll
    for (int i = 0; i < 4; i++) {
        int f = tid + i*256;
        int r = f >> 3, ch = f & 7;
        cpa16(sbase + (uint32_t)(r*PW + ch*4)*4u,
              g_Qf + base + (size_t)(q0 + r)*DK + ch*8);
    }
    stageKV(0, 0);
    CP_COMMIT();
    stageKV(1, 1);
    CP_COMMIT();

    float of[8][4];
#pragma unroll
    for (int dt = 0; dt < 8; dt++)
#pragma unroll
        for (int j = 0; j < 4; j++) of[dt][j] = 0.f;
    float m0 = -1e30f, m1 = -1e30f, l0 = 0.f, l1 = 0.f;

    const int NT = SEQ/64;
    int cb = 0;    // compute buffer = t % 3
    for (int t = 0; t < NT; t++) {
        CP_WAIT1();          // tile t's group complete (t+1 may still fly)
        __syncthreads();     // tile t visible; buffer (t-1)%3 reader-free

        uint32_t qA = sbase + qOffW*4u;
        uint32_t kA = sbase + (uint32_t)(AQ_SZ + cb*AK_SZ)*4u + bOffW*4u;
        uint32_t vA = sbase + (uint32_t)(AQ_SZ + (3 + cb)*AK_SZ)*4u + bOffW*4u;

        // S = Q . K^T
        float sacc[8][4];
#pragma unroll
        for (int nt = 0; nt < 8; nt++)
#pragma unroll
            for (int j = 0; j < 4; j++) sacc[nt][j] = 0.f;
#pragma unroll
        for (int ks = 0; ks < 4; ks++) {
            uint32_t off = (uint32_t)(ks*8)*4u;
            uint32_t qf[4];
            ldsm4(qf, qA + off);
#pragma unroll
            for (int p = 0; p < 4; p++) {
                uint32_t kb[4];
                ldsm4(kb, kA + (uint32_t)(p*16*PW)*4u + off);
                mma_fp16(sacc[2*p],   qf, kb[0], kb[1]);
                mma_fp16(sacc[2*p+1], qf, kb[2], kb[3]);
            }
        }

        // online softmax (log2 domain; Q prescaled)
        float tm0 = -1e30f, tm1 = -1e30f;
#pragma unroll
        for (int nt = 0; nt < 8; nt++) {
            tm0 = fmaxf(tm0, fmaxf(sacc[nt][0], sacc[nt][1]));
            tm1 = fmaxf(tm1, fmaxf(sacc[nt][2], sacc[nt][3]));
        }
        tm0 = fmaxf(tm0, __shfl_xor_sync(0xffffffffu, tm0, 1));
        tm0 = fmaxf(tm0, __shfl_xor_sync(0xffffffffu, tm0, 2));
        tm1 = fmaxf(tm1, __shfl_xor_sync(0xffffffffu, tm1, 1));
        tm1 = fmaxf(tm1, __shfl_xor_sync(0xffffffffu, tm1, 2));

        float mn0 = fmaxf(m0, tm0), mn1 = fmaxf(m1, tm1);
        float a0 = ex2f(m0 - mn0), a1 = ex2f(m1 - mn1);
        m0 = mn0; m1 = mn1;

        // P via f16x2 ex2, directly in pa register layout
        uint32_t pp[16];
        float rs0 = 0.f, rs1 = 0.f;
#pragma unroll
        for (int nt = 0; nt < 8; nt++) {
            pp[2*nt]   = h2ex2(packh2(sacc[nt][0] - mn0, sacc[nt][1] - mn0));
            pp[2*nt+1] = h2ex2(packh2(sacc[nt][2] - mn1, sacc[nt][3] - mn1));
            float2 u0 = h2unpack(pp[2*nt]);
            float2 u1 = h2unpack(pp[2*nt+1]);
            rs0 += u0.x + u0.y;
            rs1 += u1.x + u1.y;
        }
        rs0 += __shfl_xor_sync(0xffffffffu, rs0, 1);
        rs0 += __shfl_xor_sync(0xffffffffu, rs0, 2);
        rs1 += __shfl_xor_sync(0xffffffffu, rs1, 1);
        rs1 += __shfl_xor_sync(0xffffffffu, rs1, 2);
        l0 = l0 * a0 + rs0;
        l1 = l1 * a1 + rs1;
#pragma unroll
        for (int dt = 0; dt < 8; dt++) {
            of[dt][0] *= a0; of[dt][1] *= a0;
            of[dt][2] *= a1; of[dt][3] *= a1;
        }

        // O += P . V (pa comes straight from pp)
#pragma unroll
        for (int ks = 0; ks < 4; ks++) {
            uint32_t off = (uint32_t)(ks*8)*4u;
#pragma unroll
            for (int p = 0; p < 4; p++) {
                uint32_t vb[4];
                ldsm4(vb, vA + (uint32_t)(p*16*PW)*4u + off);
                mma_fp16(of[2*p],   &pp[4*ks], vb[0], vb[1]);
                mma_fp16(of[2*p+1], &pp[4*ks], vb[2], vb[3]);
            }
        }

        // prefetch tile t+2 into the buffer just freed ((t-1)%3 == (t+2)%3)
        int nb = cb + 2; if (nb >= 3) nb -= 3;
        if (t + 2 < NT) stageKV(t + 2, nb);
        CP_COMMIT();         // uniform depth (possibly empty)
        cb = (cb == 2) ? 0 : cb + 1;
    }

    // epilogue: normalize -> fp16 ctx, [b, s, h, d] concat layout
    float inv0 = 1.0f / l0, inv1 = 1.0f / l1;
    const int b = bh >> 4, h = bh & 15;
    const int sg0 = q0 + w*16 + g, sg1 = sg0 + 8;
#pragma unroll
    for (int dt = 0; dt < 8; dt++) {
        int dcol = dt*8 + 2*tg;
        size_t i0 = ((size_t)(b*SEQ + sg0) * NH + h) * DK + dcol;
        size_t i1 = ((size_t)(b*SEQ + sg1) * NH + h) * DK + dcol;
        *(uint32_t*)&g_Cf[i0] = packh2(of[dt][0]*inv0, of[dt][1]*inv0);
        *(uint32_t*)&g_Cf[i1] = packh2(of[dt][2]*inv1, of[dt][3]*inv1);
    }
}

// ---------------------------------------------------------------------------
extern "C" void kernel_launch(void* const* d_in, const int* in_sizes, int n_in,
                              void* d_out, int out_size)
{
    const float* Xq = (const float*)d_in[0];
    const float* Xk = (const float*)d_in[1];
    const float* Xv = (const float*)d_in[2];
    const float* Wq = (const float*)d_in[3];
    const float* bq = (const float*)d_in[4];
    const float* Wk = (const float*)d_in[5];
    const float* bk = (const float*)d_in[6];
    const float* Wv = (const float*)d_in[7];
    const float* bv = (const float*)d_in[8];
    const float* Wo = (const float*)d_in[9];
    const float* bo = (const float*)d_in[10];
    float* out = (float*)d_out;

    cudaFuncSetAttribute(gemm_fp16,
                         cudaFuncAttributeMaxDynamicSharedMemorySize,
                         GEMM_SMEM_BYTES);
    cudaFuncSetAttribute(attn_fp16,
                         cudaFuncAttributeMaxDynamicSharedMemorySize,
                         ATTN_SMEM_BYTES);

    prep<<<dim3(1024, 1, 7), 256>>>(Wq, Wk, Wv, Wo, Xq, Xk, Xv);

    dim3 gq(DM/128, MROWS/128, 3);   // fused QKV: 8 x 32 x 3 = 768 blocks
    gemm_fp16<<<gq, 256, GEMM_SMEM_BYTES>>>(1, bq, bk, bv, nullptr);

    dim3 ga(SEQ/128, BATCH*NH);      // 16 x 32
    attn_fp16<<<ga, 256, ATTN_SMEM_BYTES>>>();

    dim3 gp(DM/128, MROWS/128, 1);   // out projection: 256 blocks
    gemm_fp16<<<gp, 256, GEMM_SMEM_BYTES>>>(0, bo, bo, bo, out);
}